// round 15
// baseline (speedup 1.0000x reference)
#include <cuda_runtime.h>

#define NU_MAX 100000
#define NI_MAX 50000
#define EDIM 32

// ---------------- device scratch ----------------
__device__ __align__(256) float g_U0[NU_MAX * EDIM];
__device__ __align__(256) float g_U1[NU_MAX * EDIM];
__device__ __align__(256) float g_U2[NU_MAX * EDIM];
__device__ __align__(256) float g_U3[NU_MAX * EDIM];
__device__ __align__(256) float g_I0[NI_MAX * EDIM];
__device__ __align__(256) float g_I1[NI_MAX * EDIM];
__device__ __align__(256) float g_P1[NI_MAX * EDIM];
__device__ __align__(256) float g_P2[NU_MAX * EDIM];
__device__ __align__(256) float g_H1[NI_MAX * EDIM];
__device__ __align__(256) float g_H2[NU_MAX * EDIM];
__device__ __align__(256) float g_A [NU_MAX * EDIM];
__device__ __align__(256) float g_B [NU_MAX * EDIM];
__device__ float g_S1[NI_MAX];
__device__ float g_S2[NU_MAX];
__device__ float g_S3[NU_MAX];
__device__ float g_S4[NU_MAX];
__device__ float g_stats[64];

__device__ __forceinline__ void red_add_v4(float* p, float4 v) {
    asm volatile("red.global.add.v4.f32 [%0], {%1,%2,%3,%4};"
                 :: "l"(p), "f"(v.x), "f"(v.y), "f"(v.z), "f"(v.w) : "memory");
}
__device__ __forceinline__ float lrelu02(float t) { return t > 0.f ? t : 0.2f * t; }

// ---------------- fused projections, persistent: user x4 + item x2 ----------------
// Also zeroes ALL accumulation scratch (H1/H2/A/B, S1..S4, stats) before its GEMM
// loop — kernel-boundary ordering guarantees consumers see zeroed buffers.
__global__ void proj_all_kernel(const float* __restrict__ user,
                                const float* __restrict__ W0, const float* __restrict__ b0,
                                const float* __restrict__ W1, const float* __restrict__ b1,
                                const float* __restrict__ W2, const float* __restrict__ b2,
                                const float* __restrict__ W3, const float* __restrict__ b3,
                                float* __restrict__ O0, float* __restrict__ O1,
                                float* __restrict__ O2, float* __restrict__ O3,
                                int nu, int nbu,
                                const float* __restrict__ item,
                                const float* __restrict__ V0, const float* __restrict__ c0,
                                const float* __restrict__ V1, const float* __restrict__ c1,
                                float* __restrict__ Q0, float* __restrict__ Q1, int ni) {
    __shared__ float Wsh[4][32 * 36];
    int tid = threadIdx.x;

    // ---- integrated scratch zeroing (grid-stride, float4) ----
    {
        long i0 = (long)blockIdx.x * blockDim.x + tid;
        long stride = (long)gridDim.x * blockDim.x;
        long nuQ = (long)nu * 8, niQ = (long)ni * 8;   // float4 counts
        float4 z4 = make_float4(0.f, 0.f, 0.f, 0.f);
        for (long i = i0; i < nuQ; i += stride) {
            ((float4*)g_H2)[i] = z4;
            ((float4*)g_A)[i]  = z4;
            ((float4*)g_B)[i]  = z4;
        }
        for (long i = i0; i < niQ; i += stride) ((float4*)g_H1)[i] = z4;
        for (long i = i0; i < nu;  i += stride) { g_S2[i] = 0.f; g_S3[i] = 0.f; g_S4[i] = 0.f; }
        for (long i = i0; i < ni;  i += stride) g_S1[i] = 0.f;
        if (i0 < 64) g_stats[i0] = 0.f;
    }

    bool second = (int)blockIdx.x >= nbu;
    int b = second ? (int)blockIdx.x - nbu : (int)blockIdx.x;
    int nblk = second ? (int)gridDim.x - nbu : nbu;
    int nmat = second ? 2 : 4;
    const float* Ws[4];
    if (second) { Ws[0] = V0; Ws[1] = V1; Ws[2] = V0; Ws[3] = V1; }
    else        { Ws[0] = W0; Ws[1] = W1; Ws[2] = W2; Ws[3] = W3; }
    for (int i = tid; i < nmat * 1024; i += blockDim.x) {
        int m = i >> 10, r = (i >> 5) & 31, c = i & 31;
        Wsh[m][r * 36 + c] = Ws[m][r * 32 + c];
    }
    __syncthreads();
    int warp = tid >> 5, lane = tid & 31;
    int rstep = nblk * 8;
    if (second) {
        float a0b = c0[lane], a1b = c1[lane];
        for (int row = b * 8 + warp; row < ni; row += rstep) {
            float h = item[row * 32 + lane];
            float a0 = a0b, a1 = a1b;
#pragma unroll
            for (int k = 0; k < 32; k += 4) {
                float h0 = __shfl_sync(0xffffffffu, h, k);
                float h1 = __shfl_sync(0xffffffffu, h, k + 1);
                float h2 = __shfl_sync(0xffffffffu, h, k + 2);
                float h3 = __shfl_sync(0xffffffffu, h, k + 3);
                float4 w;
                w = *(const float4*)&Wsh[0][lane * 36 + k]; a0 += h0 * w.x + h1 * w.y + h2 * w.z + h3 * w.w;
                w = *(const float4*)&Wsh[1][lane * 36 + k]; a1 += h0 * w.x + h1 * w.y + h2 * w.z + h3 * w.w;
            }
            Q0[row * 32 + lane] = a0;
            Q1[row * 32 + lane] = a1;
        }
    } else {
        float b0v = b0[lane], b1v = b1[lane], b2v = b2[lane], b3v = b3[lane];
        for (int row = b * 8 + warp; row < nu; row += rstep) {
            float h = user[row * 32 + lane];
            float a0 = b0v, a1 = b1v, a2 = b2v, a3 = b3v;
#pragma unroll
            for (int k = 0; k < 32; k += 4) {
                float h0 = __shfl_sync(0xffffffffu, h, k);
                float h1 = __shfl_sync(0xffffffffu, h, k + 1);
                float h2 = __shfl_sync(0xffffffffu, h, k + 2);
                float h3 = __shfl_sync(0xffffffffu, h, k + 3);
                float4 w;
                w = *(const float4*)&Wsh[0][lane * 36 + k]; a0 += h0 * w.x + h1 * w.y + h2 * w.z + h3 * w.w;
                w = *(const float4*)&Wsh[1][lane * 36 + k]; a1 += h0 * w.x + h1 * w.y + h2 * w.z + h3 * w.w;
                w = *(const float4*)&Wsh[2][lane * 36 + k]; a2 += h0 * w.x + h1 * w.y + h2 * w.z + h3 * w.w;
                w = *(const float4*)&Wsh[3][lane * 36 + k]; a3 += h0 * w.x + h1 * w.y + h2 * w.z + h3 * w.w;
            }
            O0[row * 32 + lane] = a0;
            O1[row * 32 + lane] = a1;
            O2[row * 32 + lane] = a2;
            O3[row * 32 + lane] = a3;
        }
    }
}

// ---------------- H1/H2 projection (scaled by 1/S), persistent, two segments ------
__global__ void projHH_kernel(const float* __restrict__ inA, const float* __restrict__ sA,
                              const float* __restrict__ WA, const float* __restrict__ bA,
                              float* __restrict__ OA, int nA, int nbA,
                              const float* __restrict__ inB, const float* __restrict__ sB,
                              const float* __restrict__ WB, const float* __restrict__ bB,
                              float* __restrict__ OB, int nB) {
    bool second = (int)blockIdx.x >= nbA;
    int b = second ? (int)blockIdx.x - nbA : (int)blockIdx.x;
    int nblk = second ? (int)gridDim.x - nbA : nbA;
    const float* in = second ? inB : inA;
    const float* sd = second ? sB : sA;
    const float* W  = second ? WB : WA;
    const float* bi = second ? bB : bA;
    float* out = second ? OB : OA;
    int nrows = second ? nB : nA;

    __shared__ float Wsh[32 * 36];
    int tid = threadIdx.x;
    for (int i = tid; i < 1024; i += blockDim.x)
        Wsh[(i >> 5) * 36 + (i & 31)] = W[i];
    __syncthreads();
    int warp = tid >> 5, lane = tid & 31;
    float bias = bi[lane];
    int rstep = nblk * 8;
    for (int row = b * 8 + warp; row < nrows; row += rstep) {
        float sv = sd[row];
        float scale = (sv > 0.f) ? (1.0f / sv) : 0.0f;
        float h = in[row * 32 + lane] * scale;
        float acc = bias;
#pragma unroll
        for (int k = 0; k < 32; k += 4) {
            float h0 = __shfl_sync(0xffffffffu, h, k);
            float h1 = __shfl_sync(0xffffffffu, h, k + 1);
            float h2 = __shfl_sync(0xffffffffu, h, k + 2);
            float h3 = __shfl_sync(0xffffffffu, h, k + 3);
            float4 w = *(const float4*)&Wsh[lane * 36 + k];
            acc += h0 * w.x + h1 * w.y + h2 * w.z + h3 * w.w;
        }
        out[row * 32 + lane] = acc;
    }
}

// ---------------- core edge step: 8 lanes per edge, float4 channels ----------------
__device__ __forceinline__ void edge_step(
    int si, int di, int q, bool valid,
    const float4* __restrict__ fs, const float4* __restrict__ fd,
    float4 a, float* __restrict__ out, float* __restrict__ den)
{
    float4 fsv = __ldg(&fs[si * 8 + q]);
    float4 fdv = __ldg(&fd[di * 8 + q]);
    float s = lrelu02(fsv.x + fdv.x) * a.x + lrelu02(fsv.y + fdv.y) * a.y
            + lrelu02(fsv.z + fdv.z) * a.z + lrelu02(fsv.w + fdv.w) * a.w;
    s += __shfl_xor_sync(0xffffffffu, s, 1);
    s += __shfl_xor_sync(0xffffffffu, s, 2);
    s += __shfl_xor_sync(0xffffffffu, s, 4);
    float ex = __expf(s);
    if (valid) {
        float4 r = make_float4(ex * fsv.x, ex * fsv.y, ex * fsv.z, ex * fsv.w);
        red_add_v4(&out[di * 32 + q * 4], r);
        if (q == 0) atomicAdd(&den[di], ex);
    }
}

// ---------------- layer-1 fused: both directions, 3 edges per thread (ILP 6) -------
// Chunk decomposition is exact: a thread owns edge e0 ONLY if e0 < third; chunks
// k=1,2 additionally bounded by ne. (R14 bug: overrun threads with e0 >= third
// passed the e0 < ne guard and double-counted edges.)
__global__ void edge_l1_kernel(const int* __restrict__ src, const int* __restrict__ dst,
                               const float4* __restrict__ fsA, const float4* __restrict__ fdA,
                               const float4* __restrict__ attnA, float* __restrict__ outA, float* __restrict__ denA,
                               const float4* __restrict__ fsB, const float4* __restrict__ fdB,
                               const float4* __restrict__ attnB, float* __restrict__ outB, float* __restrict__ denB,
                               int ne, int third) {
    int t = blockIdx.x * blockDim.x + threadIdx.x;
    int e0 = t >> 3;
    int q = t & 7;
    float4 aA = __ldg(&attnA[q]);
    float4 aB = __ldg(&attnB[q]);
    int e1 = e0 + third;
    int e2 = e0 + 2 * third;
    bool in0 = e0 < third;
    bool v0 = in0;                   // e0 < third <= ne
    bool v1 = in0 && (e1 < ne);
    bool v2 = in0 && (e2 < ne);
    int c0 = v0 ? e0 : 0;
    int c1 = v1 ? e1 : 0;
    int c2 = v2 ? e2 : 0;
    int u0 = __ldg(&src[c0]), w0 = __ldg(&dst[c0]);
    int u1 = __ldg(&src[c1]), w1 = __ldg(&dst[c1]);
    int u2 = __ldg(&src[c2]), w2 = __ldg(&dst[c2]);
    edge_step(u0, w0, q, v0, fsA, fdA, aA, outA, denA);  // user -> item ('rate')
    edge_step(u1, w1, q, v1, fsA, fdA, aA, outA, denA);
    edge_step(u2, w2, q, v2, fsA, fdA, aA, outA, denA);
    edge_step(w0, u0, q, v0, fsB, fdB, aB, outB, denB);  // item -> user ('rated-by')
    edge_step(w1, u1, q, v1, fsB, fdB, aB, outB, denB);
    edge_step(w2, u2, q, v2, fsB, fdB, aB, outB, denB);
}

// ---------------- layer-2: rby (3 edges/thread) + trust (2 edges/thread) -----------
// Same exact-chunk guards: rby gated on e0 < third1, trust gated on e0 < half2.
__global__ void edge_l2_kernel(
    const int* __restrict__ s1, const int* __restrict__ d1,
    const float4* __restrict__ fs1, const float4* __restrict__ fd1,
    const float4* __restrict__ a1, float* __restrict__ o1, float* __restrict__ den1,
    int ne1, int third1,
    const int* __restrict__ s2, const int* __restrict__ d2,
    const float4* __restrict__ fs2, const float4* __restrict__ fd2,
    const float4* __restrict__ a2, float* __restrict__ o2, float* __restrict__ den2,
    int ne2, int half2)
{
    int t = blockIdx.x * blockDim.x + threadIdx.x;
    int e0 = t >> 3;
    int q = t & 7;
    float4 aa1 = __ldg(&a1[q]);
    float4 aa2 = __ldg(&a2[q]);
    int e1 = e0 + third1;
    int e2 = e0 + 2 * third1;
    int f1 = e0 + half2;
    bool in1 = e0 < third1;
    bool v0 = in1;
    bool v1 = in1 && (e1 < ne1);
    bool v2 = in1 && (e2 < ne1);
    bool in2 = e0 < half2;
    bool w0v = in2;
    bool w1v = in2 && (f1 < ne2);
    int c0 = v0 ? e0 : 0;
    int c1 = v1 ? e1 : 0;
    int c2 = v2 ? e2 : 0;
    int g0 = w0v ? e0 : 0;
    int g1 = w1v ? f1 : 0;
    int u0 = __ldg(&s1[c0]), x0 = __ldg(&d1[c0]);
    int u1 = __ldg(&s1[c1]), x1 = __ldg(&d1[c1]);
    int u2 = __ldg(&s1[c2]), x2 = __ldg(&d1[c2]);
    int t0 = __ldg(&s2[g0]), y0 = __ldg(&d2[g0]);
    int t1 = __ldg(&s2[g1]), y1 = __ldg(&d2[g1]);
    edge_step(u0, x0, q, v0, fs1, fd1, aa1, o1, den1);
    edge_step(u1, x1, q, v1, fs1, fd1, aa1, o1, den1);
    edge_step(u2, x2, q, v2, fs1, fd1, aa1, o1, den1);
    edge_step(t0, y0, q, w0v, fs2, fd2, aa2, o2, den2);
    edge_step(t1, y1, q, w1v, fs2, fd2, aa2, o2, den2);
}

// ---------------- output head + fused BN stats, persistent ----------------
__global__ void head_kernel(const float* __restrict__ A, const float* __restrict__ B,
                            const float* __restrict__ s3, const float* __restrict__ s4,
                            const float* __restrict__ Wout, const float* __restrict__ bout,
                            float* __restrict__ y, int nu) {
    __shared__ float WshA[32 * 36];   // Wout[out][0..31]
    __shared__ float WshB[32 * 36];   // Wout[out][32..63]
    __shared__ float ssum[32], ssq[32];
    int tid = threadIdx.x;
    for (int i = tid; i < 1024; i += blockDim.x) {
        int r = i >> 5, c = i & 31;
        WshA[r * 36 + c] = Wout[r * 64 + c];
        WshB[r * 36 + c] = Wout[r * 64 + 32 + c];
    }
    if (tid < 32) { ssum[tid] = 0.f; ssq[tid] = 0.f; }
    __syncthreads();
    int warp = tid >> 5, lane = tid & 31;
    float bias = bout[lane];
    float lsum = 0.f, lsq = 0.f;
    int rstep = gridDim.x * 8;
    for (int row = blockIdx.x * 8 + warp; row < nu; row += rstep) {
        float sa = s3[row]; sa = (sa > 0.f) ? (1.0f / sa) : 0.0f;
        float sb = s4[row]; sb = (sb > 0.f) ? (1.0f / sb) : 0.0f;
        float av = A[row * 32 + lane] * sa;
        float bv = B[row * 32 + lane] * sb;
        float acc = bias;
#pragma unroll
        for (int k = 0; k < 32; k += 4) {
            float a0 = __shfl_sync(0xffffffffu, av, k);
            float a1 = __shfl_sync(0xffffffffu, av, k + 1);
            float a2 = __shfl_sync(0xffffffffu, av, k + 2);
            float a3 = __shfl_sync(0xffffffffu, av, k + 3);
            float b0 = __shfl_sync(0xffffffffu, bv, k);
            float b1 = __shfl_sync(0xffffffffu, bv, k + 1);
            float b2 = __shfl_sync(0xffffffffu, bv, k + 2);
            float b3 = __shfl_sync(0xffffffffu, bv, k + 3);
            float4 wa = *(const float4*)&WshA[lane * 36 + k];
            float4 wb = *(const float4*)&WshB[lane * 36 + k];
            acc += a0 * wa.x + a1 * wa.y + a2 * wa.z + a3 * wa.w;
            acc += b0 * wb.x + b1 * wb.y + b2 * wb.z + b3 * wb.w;
        }
        y[row * 32 + lane] = acc;
        lsum += acc;
        lsq += acc * acc;
    }
    atomicAdd(&ssum[lane], lsum);
    atomicAdd(&ssq[lane], lsq);
    __syncthreads();
    if (tid < 32) {
        atomicAdd(&g_stats[tid], ssum[tid]);
        atomicAdd(&g_stats[32 + tid], ssq[tid]);
    }
}

// ---------------- finalize: BN + LeakyReLU(0.01) ----------------
__global__ void finalize_kernel(float* __restrict__ y, const float* __restrict__ gamma,
                                const float* __restrict__ beta, int nu) {
    int i = blockIdx.x * blockDim.x + threadIdx.x;
    if (i >= nu * 32) return;
    int c = i & 31;
    float inv_n = 1.0f / (float)nu;
    float mean = g_stats[c] * inv_n;
    float var = g_stats[32 + c] * inv_n - mean * mean;
    float v = (y[i] - mean) * rsqrtf(var + 1e-5f) * gamma[c] + beta[c];
    y[i] = (v > 0.f) ? v : 0.01f * v;
}

// ---------------- host launch ----------------
extern "C" void kernel_launch(void* const* d_in, const int* in_sizes, int n_in,
                              void* d_out, int out_size) {
    const float* user = (const float*)d_in[0];
    const float* item = (const float*)d_in[1];
    const int* rate_src  = (const int*)d_in[2];
    const int* rate_dst  = (const int*)d_in[3];
    const int* trust_src = (const int*)d_in[4];
    const int* trust_dst = (const int*)d_in[5];
    const float* p[20];
    for (int i = 0; i < 20; ++i) p[i] = (const float*)d_in[6 + i];
    const float* Wout  = (const float*)d_in[26];
    const float* bout  = (const float*)d_in[27];
    const float* gamma = (const float*)d_in[28];
    const float* beta  = (const float*)d_in[29];

    int nu = in_sizes[0] / EDIM;
    int ni = in_sizes[1] / EDIM;
    int ne_rate  = in_sizes[2];
    int ne_trust = in_sizes[4];
    float* y = (float*)d_out;

    float *U0, *U1, *U2, *U3, *I0, *I1, *P1, *P2, *H1, *H2, *A, *B, *S1, *S2, *S3, *S4;
    cudaGetSymbolAddress((void**)&U0, g_U0);
    cudaGetSymbolAddress((void**)&U1, g_U1);
    cudaGetSymbolAddress((void**)&U2, g_U2);
    cudaGetSymbolAddress((void**)&U3, g_U3);
    cudaGetSymbolAddress((void**)&I0, g_I0);
    cudaGetSymbolAddress((void**)&I1, g_I1);
    cudaGetSymbolAddress((void**)&P1, g_P1);
    cudaGetSymbolAddress((void**)&P2, g_P2);
    cudaGetSymbolAddress((void**)&H1, g_H1);
    cudaGetSymbolAddress((void**)&H2, g_H2);
    cudaGetSymbolAddress((void**)&A,  g_A);
    cudaGetSymbolAddress((void**)&B,  g_B);
    cudaGetSymbolAddress((void**)&S1, g_S1);
    cudaGetSymbolAddress((void**)&S2, g_S2);
    cudaGetSymbolAddress((void**)&S3, g_S3);
    cudaGetSymbolAddress((void**)&S4, g_S4);

    const int T = 256;
    int third_r = (ne_rate + 2) / 3;
    int half_t  = (ne_trust + 1) / 2;
    int gb_l1 = (third_r * 8 + T - 1) / T;
    int slots_l2 = (third_r > half_t) ? third_r : half_t;
    int gb_l2 = (slots_l2 * 8 + T - 1) / T;

    // persistent block counts (multiples of SM count 148)
    const int NBU = 592;   // user segment of proj_all (4 waves)
    const int NBI = 296;   // item segment of proj_all
    const int NBA = 296;   // projHH segment A (ni rows)
    const int NBB = 592;   // projHH segment B (nu rows)
    const int NBH = 592;   // head

    // all 6 input projections + scratch zeroing in one persistent segmented launch
    proj_all_kernel<<<NBU + NBI, T>>>(user, p[0], p[1], p[7], p[8], p[12], p[13], p[17], p[18],
                                      U0, U1, U2, U3, nu, NBU,
                                      item, p[2], p[3], p[5], p[6], I0, I1, ni);

    // layer 1 fused edge pass (rate + rated-by share the edge list), 3 edges/thread
    edge_l1_kernel<<<gb_l1, T>>>(rate_src, rate_dst,
                                 (const float4*)U0, (const float4*)I0, (const float4*)p[4], H1, S1,
                                 (const float4*)I1, (const float4*)U1, (const float4*)p[9], H2, S2,
                                 ne_rate, third_r);

    // layer-2 src projections (normalization folded via S1/S2), persistent
    projHH_kernel<<<NBA + NBB, T>>>(H1, S1, p[10], p[11], P1, ni, NBA,
                                    H2, S2, p[15], p[16], P2, nu);

    // layer-2 edge pass: rby (3 edges/thread) + trust (2 edges/thread)
    edge_l2_kernel<<<gb_l2, T>>>(
        rate_dst, rate_src, (const float4*)P1, (const float4*)U2, (const float4*)p[14], A, S3,
        ne_rate, third_r,
        trust_src, trust_dst, (const float4*)P2, (const float4*)U3, (const float4*)p[19], B, S4,
        ne_trust, half_t);

    // head (+fused BN stats) + finalize
    head_kernel<<<NBH, T>>>(A, B, S3, S4, Wout, bout, y, nu);
    finalize_kernel<<<(nu * EDIM + T - 1) / T, T>>>(y, gamma, beta, nu);
}

// round 17
// speedup vs baseline: 1.0213x; 1.0213x over previous
#include <cuda_runtime.h>

#define NU_MAX 100000
#define NI_MAX 50000
#define EDIM 32

// ---------------- device scratch ----------------
__device__ __align__(256) float g_U0[NU_MAX * EDIM];
__device__ __align__(256) float g_U1[NU_MAX * EDIM];
__device__ __align__(256) float g_U2[NU_MAX * EDIM];
__device__ __align__(256) float g_U3[NU_MAX * EDIM];
__device__ __align__(256) float g_I0[NI_MAX * EDIM];
__device__ __align__(256) float g_I1[NI_MAX * EDIM];
__device__ __align__(256) float g_P1[NI_MAX * EDIM];
__device__ __align__(256) float g_P2[NU_MAX * EDIM];
__device__ __align__(256) float g_H1[NI_MAX * EDIM];
__device__ __align__(256) float g_H2[NU_MAX * EDIM];
__device__ __align__(256) float g_A [NU_MAX * EDIM];
__device__ __align__(256) float g_B [NU_MAX * EDIM];
__device__ float g_S1[NI_MAX];
__device__ float g_S2[NU_MAX];
__device__ float g_S3[NU_MAX];
__device__ float g_S4[NU_MAX];
__device__ __align__(16) float g_stats[64];

__device__ __forceinline__ void red_add_v4(float* p, float4 v) {
    asm volatile("red.global.add.v4.f32 [%0], {%1,%2,%3,%4};"
                 :: "l"(p), "f"(v.x), "f"(v.y), "f"(v.z), "f"(v.w) : "memory");
}
__device__ __forceinline__ float lrelu02(float t) { return t > 0.f ? t : 0.2f * t; }

// ---------------- fused projections, persistent: user x4 + item x2 ----------------
// Also zeroes ALL accumulation scratch (H1/H2/A/B, S1..S4, stats) before its GEMM
// loop — kernel-boundary ordering guarantees consumers see zeroed buffers.
__global__ void proj_all_kernel(const float* __restrict__ user,
                                const float* __restrict__ W0, const float* __restrict__ b0,
                                const float* __restrict__ W1, const float* __restrict__ b1,
                                const float* __restrict__ W2, const float* __restrict__ b2,
                                const float* __restrict__ W3, const float* __restrict__ b3,
                                float* __restrict__ O0, float* __restrict__ O1,
                                float* __restrict__ O2, float* __restrict__ O3,
                                int nu, int nbu,
                                const float* __restrict__ item,
                                const float* __restrict__ V0, const float* __restrict__ c0,
                                const float* __restrict__ V1, const float* __restrict__ c1,
                                float* __restrict__ Q0, float* __restrict__ Q1, int ni) {
    __shared__ float Wsh[4][32 * 36];
    int tid = threadIdx.x;

    // ---- integrated scratch zeroing (grid-stride, float4) ----
    {
        long i0 = (long)blockIdx.x * blockDim.x + tid;
        long stride = (long)gridDim.x * blockDim.x;
        long nuQ = (long)nu * 8, niQ = (long)ni * 8;   // float4 counts
        float4 z4 = make_float4(0.f, 0.f, 0.f, 0.f);
        for (long i = i0; i < nuQ; i += stride) {
            ((float4*)g_H2)[i] = z4;
            ((float4*)g_A)[i]  = z4;
            ((float4*)g_B)[i]  = z4;
        }
        for (long i = i0; i < niQ; i += stride) ((float4*)g_H1)[i] = z4;
        for (long i = i0; i < nu;  i += stride) { g_S2[i] = 0.f; g_S3[i] = 0.f; g_S4[i] = 0.f; }
        for (long i = i0; i < ni;  i += stride) g_S1[i] = 0.f;
        if (i0 < 64) g_stats[i0] = 0.f;
    }

    bool second = (int)blockIdx.x >= nbu;
    int b = second ? (int)blockIdx.x - nbu : (int)blockIdx.x;
    int nblk = second ? (int)gridDim.x - nbu : nbu;
    int nmat = second ? 2 : 4;
    const float* Ws[4];
    if (second) { Ws[0] = V0; Ws[1] = V1; Ws[2] = V0; Ws[3] = V1; }
    else        { Ws[0] = W0; Ws[1] = W1; Ws[2] = W2; Ws[3] = W3; }
    for (int i = tid; i < nmat * 1024; i += blockDim.x) {
        int m = i >> 10, r = (i >> 5) & 31, c = i & 31;
        Wsh[m][r * 36 + c] = Ws[m][r * 32 + c];
    }
    __syncthreads();
    int warp = tid >> 5, lane = tid & 31;
    int rstep = nblk * 8;
    if (second) {
        float a0b = c0[lane], a1b = c1[lane];
        for (int row = b * 8 + warp; row < ni; row += rstep) {
            float h = item[row * 32 + lane];
            float a0 = a0b, a1 = a1b;
#pragma unroll
            for (int k = 0; k < 32; k += 4) {
                float h0 = __shfl_sync(0xffffffffu, h, k);
                float h1 = __shfl_sync(0xffffffffu, h, k + 1);
                float h2 = __shfl_sync(0xffffffffu, h, k + 2);
                float h3 = __shfl_sync(0xffffffffu, h, k + 3);
                float4 w;
                w = *(const float4*)&Wsh[0][lane * 36 + k]; a0 += h0 * w.x + h1 * w.y + h2 * w.z + h3 * w.w;
                w = *(const float4*)&Wsh[1][lane * 36 + k]; a1 += h0 * w.x + h1 * w.y + h2 * w.z + h3 * w.w;
            }
            Q0[row * 32 + lane] = a0;
            Q1[row * 32 + lane] = a1;
        }
    } else {
        float b0v = b0[lane], b1v = b1[lane], b2v = b2[lane], b3v = b3[lane];
        for (int row = b * 8 + warp; row < nu; row += rstep) {
            float h = user[row * 32 + lane];
            float a0 = b0v, a1 = b1v, a2 = b2v, a3 = b3v;
#pragma unroll
            for (int k = 0; k < 32; k += 4) {
                float h0 = __shfl_sync(0xffffffffu, h, k);
                float h1 = __shfl_sync(0xffffffffu, h, k + 1);
                float h2 = __shfl_sync(0xffffffffu, h, k + 2);
                float h3 = __shfl_sync(0xffffffffu, h, k + 3);
                float4 w;
                w = *(const float4*)&Wsh[0][lane * 36 + k]; a0 += h0 * w.x + h1 * w.y + h2 * w.z + h3 * w.w;
                w = *(const float4*)&Wsh[1][lane * 36 + k]; a1 += h0 * w.x + h1 * w.y + h2 * w.z + h3 * w.w;
                w = *(const float4*)&Wsh[2][lane * 36 + k]; a2 += h0 * w.x + h1 * w.y + h2 * w.z + h3 * w.w;
                w = *(const float4*)&Wsh[3][lane * 36 + k]; a3 += h0 * w.x + h1 * w.y + h2 * w.z + h3 * w.w;
            }
            O0[row * 32 + lane] = a0;
            O1[row * 32 + lane] = a1;
            O2[row * 32 + lane] = a2;
            O3[row * 32 + lane] = a3;
        }
    }
}

// ---------------- H1/H2 projection (scaled by 1/S), persistent, two segments ------
__global__ void projHH_kernel(const float* __restrict__ inA, const float* __restrict__ sA,
                              const float* __restrict__ WA, const float* __restrict__ bA,
                              float* __restrict__ OA, int nA, int nbA,
                              const float* __restrict__ inB, const float* __restrict__ sB,
                              const float* __restrict__ WB, const float* __restrict__ bB,
                              float* __restrict__ OB, int nB) {
    bool second = (int)blockIdx.x >= nbA;
    int b = second ? (int)blockIdx.x - nbA : (int)blockIdx.x;
    int nblk = second ? (int)gridDim.x - nbA : nbA;
    const float* in = second ? inB : inA;
    const float* sd = second ? sB : sA;
    const float* W  = second ? WB : WA;
    const float* bi = second ? bB : bA;
    float* out = second ? OB : OA;
    int nrows = second ? nB : nA;

    __shared__ float Wsh[32 * 36];
    int tid = threadIdx.x;
    for (int i = tid; i < 1024; i += blockDim.x)
        Wsh[(i >> 5) * 36 + (i & 31)] = W[i];
    __syncthreads();
    int warp = tid >> 5, lane = tid & 31;
    float bias = bi[lane];
    int rstep = nblk * 8;
    for (int row = b * 8 + warp; row < nrows; row += rstep) {
        float sv = sd[row];
        float scale = (sv > 0.f) ? (1.0f / sv) : 0.0f;
        float h = in[row * 32 + lane] * scale;
        float acc = bias;
#pragma unroll
        for (int k = 0; k < 32; k += 4) {
            float h0 = __shfl_sync(0xffffffffu, h, k);
            float h1 = __shfl_sync(0xffffffffu, h, k + 1);
            float h2 = __shfl_sync(0xffffffffu, h, k + 2);
            float h3 = __shfl_sync(0xffffffffu, h, k + 3);
            float4 w = *(const float4*)&Wsh[lane * 36 + k];
            acc += h0 * w.x + h1 * w.y + h2 * w.z + h3 * w.w;
        }
        out[row * 32 + lane] = acc;
    }
}

// ---------------- core edge step: 8 lanes per edge, float4 channels ----------------
__device__ __forceinline__ void edge_step(
    int si, int di, int q, bool valid,
    const float4* __restrict__ fs, const float4* __restrict__ fd,
    float4 a, float* __restrict__ out, float* __restrict__ den)
{
    float4 fsv = __ldg(&fs[si * 8 + q]);
    float4 fdv = __ldg(&fd[di * 8 + q]);
    float s = lrelu02(fsv.x + fdv.x) * a.x + lrelu02(fsv.y + fdv.y) * a.y
            + lrelu02(fsv.z + fdv.z) * a.z + lrelu02(fsv.w + fdv.w) * a.w;
    s += __shfl_xor_sync(0xffffffffu, s, 1);
    s += __shfl_xor_sync(0xffffffffu, s, 2);
    s += __shfl_xor_sync(0xffffffffu, s, 4);
    float ex = __expf(s);
    if (valid) {
        float4 r = make_float4(ex * fsv.x, ex * fsv.y, ex * fsv.z, ex * fsv.w);
        red_add_v4(&out[di * 32 + q * 4], r);
        if (q == 0) atomicAdd(&den[di], ex);
    }
}

// ---------------- layer-1 fused: both directions, 2 edges per thread (ILP 4) -------
__global__ void edge_l1_kernel(const int* __restrict__ src, const int* __restrict__ dst,
                               const float4* __restrict__ fsA, const float4* __restrict__ fdA,
                               const float4* __restrict__ attnA, float* __restrict__ outA, float* __restrict__ denA,
                               const float4* __restrict__ fsB, const float4* __restrict__ fdB,
                               const float4* __restrict__ attnB, float* __restrict__ outB, float* __restrict__ denB,
                               int ne, int half) {
    int t = blockIdx.x * blockDim.x + threadIdx.x;
    int e0 = t >> 3;
    int q = t & 7;
    float4 aA = __ldg(&attnA[q]);
    float4 aB = __ldg(&attnB[q]);
    int e1 = e0 + half;
    bool in0 = e0 < half;
    bool v0 = in0;                    // half <= ne
    bool v1 = in0 && (e1 < ne);
    int c0 = v0 ? e0 : 0;
    int c1 = v1 ? e1 : 0;
    int u0 = __ldg(&src[c0]), w0 = __ldg(&dst[c0]);
    int u1 = __ldg(&src[c1]), w1 = __ldg(&dst[c1]);
    edge_step(u0, w0, q, v0, fsA, fdA, aA, outA, denA);  // user -> item ('rate')
    edge_step(u1, w1, q, v1, fsA, fdA, aA, outA, denA);
    edge_step(w0, u0, q, v0, fsB, fdB, aB, outB, denB);  // item -> user ('rated-by')
    edge_step(w1, u1, q, v1, fsB, fdB, aB, outB, denB);
}

// ---------------- layer-2: rby (2 edges/thread) + trust (1 edge/thread) ------------
__global__ void edge_l2_kernel(
    const int* __restrict__ s1, const int* __restrict__ d1,
    const float4* __restrict__ fs1, const float4* __restrict__ fd1,
    const float4* __restrict__ a1, float* __restrict__ o1, float* __restrict__ den1,
    int ne1, int half1,
    const int* __restrict__ s2, const int* __restrict__ d2,
    const float4* __restrict__ fs2, const float4* __restrict__ fd2,
    const float4* __restrict__ a2, float* __restrict__ o2, float* __restrict__ den2,
    int ne2)
{
    int t = blockIdx.x * blockDim.x + threadIdx.x;
    int e0 = t >> 3;
    int q = t & 7;
    float4 aa1 = __ldg(&a1[q]);
    float4 aa2 = __ldg(&a2[q]);
    int e1 = e0 + half1;
    bool in1 = e0 < half1;
    bool v0 = in1;
    bool v1 = in1 && (e1 < ne1);
    bool v2 = e0 < ne2;
    int c0 = v0 ? e0 : 0;
    int c1 = v1 ? e1 : 0;
    int c2 = v2 ? e0 : 0;
    int u0 = __ldg(&s1[c0]), w0 = __ldg(&d1[c0]);
    int u1 = __ldg(&s1[c1]), w1 = __ldg(&d1[c1]);
    int u2 = __ldg(&s2[c2]), w2 = __ldg(&d2[c2]);
    edge_step(u0, w0, q, v0, fs1, fd1, aa1, o1, den1);
    edge_step(u1, w1, q, v1, fs1, fd1, aa1, o1, den1);
    edge_step(u2, w2, q, v2, fs2, fd2, aa2, o2, den2);
}

// ---------------- output head + fused BN stats, persistent ----------------
__global__ void head_kernel(const float* __restrict__ A, const float* __restrict__ B,
                            const float* __restrict__ s3, const float* __restrict__ s4,
                            const float* __restrict__ Wout, const float* __restrict__ bout,
                            float* __restrict__ y, int nu) {
    __shared__ float WshA[32 * 36];   // Wout[out][0..31]
    __shared__ float WshB[32 * 36];   // Wout[out][32..63]
    __shared__ float ssum[32], ssq[32];
    int tid = threadIdx.x;
    for (int i = tid; i < 1024; i += blockDim.x) {
        int r = i >> 5, c = i & 31;
        WshA[r * 36 + c] = Wout[r * 64 + c];
        WshB[r * 36 + c] = Wout[r * 64 + 32 + c];
    }
    if (tid < 32) { ssum[tid] = 0.f; ssq[tid] = 0.f; }
    __syncthreads();
    int warp = tid >> 5, lane = tid & 31;
    float bias = bout[lane];
    float lsum = 0.f, lsq = 0.f;
    int rstep = gridDim.x * 8;
    for (int row = blockIdx.x * 8 + warp; row < nu; row += rstep) {
        float sa = s3[row]; sa = (sa > 0.f) ? (1.0f / sa) : 0.0f;
        float sb = s4[row]; sb = (sb > 0.f) ? (1.0f / sb) : 0.0f;
        float av = A[row * 32 + lane] * sa;
        float bv = B[row * 32 + lane] * sb;
        float acc = bias;
#pragma unroll
        for (int k = 0; k < 32; k += 4) {
            float a0 = __shfl_sync(0xffffffffu, av, k);
            float a1 = __shfl_sync(0xffffffffu, av, k + 1);
            float a2 = __shfl_sync(0xffffffffu, av, k + 2);
            float a3 = __shfl_sync(0xffffffffu, av, k + 3);
            float b0 = __shfl_sync(0xffffffffu, bv, k);
            float b1 = __shfl_sync(0xffffffffu, bv, k + 1);
            float b2 = __shfl_sync(0xffffffffu, bv, k + 2);
            float b3 = __shfl_sync(0xffffffffu, bv, k + 3);
            float4 wa = *(const float4*)&WshA[lane * 36 + k];
            float4 wb = *(const float4*)&WshB[lane * 36 + k];
            acc += a0 * wa.x + a1 * wa.y + a2 * wa.z + a3 * wa.w;
            acc += b0 * wb.x + b1 * wb.y + b2 * wb.z + b3 * wb.w;
        }
        y[row * 32 + lane] = acc;
        lsum += acc;
        lsq += acc * acc;
    }
    atomicAdd(&ssum[lane], lsum);
    atomicAdd(&ssq[lane], lsq);
    __syncthreads();
    if (tid < 32) {
        atomicAdd(&g_stats[tid], ssum[tid]);
        atomicAdd(&g_stats[32 + tid], ssq[tid]);
    }
}

// ---------------- finalize: BN + LeakyReLU(0.01), float4 vectorized ----------------
__global__ void finalize_kernel(float* __restrict__ y, const float* __restrict__ gamma,
                                const float* __restrict__ beta, int nu) {
    int i4 = blockIdx.x * blockDim.x + threadIdx.x;        // float4 index
    if (i4 >= nu * 8) return;
    int g = i4 & 7;                                        // column group (channels 4g..4g+3)
    float inv_n = 1.0f / (float)nu;
    float4 sum4 = ((const float4*)g_stats)[g];
    float4 sq4  = ((const float4*)(g_stats + 32))[g];
    float4 gm4  = ((const float4*)gamma)[g];
    float4 bt4  = ((const float4*)beta)[g];
    float4 v = ((const float4*)y)[i4];
    float m, va;
    m = sum4.x * inv_n; va = sq4.x * inv_n - m * m;
    v.x = (v.x - m) * rsqrtf(va + 1e-5f) * gm4.x + bt4.x;
    m = sum4.y * inv_n; va = sq4.y * inv_n - m * m;
    v.y = (v.y - m) * rsqrtf(va + 1e-5f) * gm4.y + bt4.y;
    m = sum4.z * inv_n; va = sq4.z * inv_n - m * m;
    v.z = (v.z - m) * rsqrtf(va + 1e-5f) * gm4.z + bt4.z;
    m = sum4.w * inv_n; va = sq4.w * inv_n - m * m;
    v.w = (v.w - m) * rsqrtf(va + 1e-5f) * gm4.w + bt4.w;
    v.x = (v.x > 0.f) ? v.x : 0.01f * v.x;
    v.y = (v.y > 0.f) ? v.y : 0.01f * v.y;
    v.z = (v.z > 0.f) ? v.z : 0.01f * v.z;
    v.w = (v.w > 0.f) ? v.w : 0.01f * v.w;
    ((float4*)y)[i4] = v;
}

// ---------------- host launch ----------------
extern "C" void kernel_launch(void* const* d_in, const int* in_sizes, int n_in,
                              void* d_out, int out_size) {
    const float* user = (const float*)d_in[0];
    const float* item = (const float*)d_in[1];
    const int* rate_src  = (const int*)d_in[2];
    const int* rate_dst  = (const int*)d_in[3];
    const int* trust_src = (const int*)d_in[4];
    const int* trust_dst = (const int*)d_in[5];
    const float* p[20];
    for (int i = 0; i < 20; ++i) p[i] = (const float*)d_in[6 + i];
    const float* Wout  = (const float*)d_in[26];
    const float* bout  = (const float*)d_in[27];
    const float* gamma = (const float*)d_in[28];
    const float* beta  = (const float*)d_in[29];

    int nu = in_sizes[0] / EDIM;
    int ni = in_sizes[1] / EDIM;
    int ne_rate  = in_sizes[2];
    int ne_trust = in_sizes[4];
    float* y = (float*)d_out;

    float *U0, *U1, *U2, *U3, *I0, *I1, *P1, *P2, *H1, *H2, *A, *B, *S1, *S2, *S3, *S4;
    cudaGetSymbolAddress((void**)&U0, g_U0);
    cudaGetSymbolAddress((void**)&U1, g_U1);
    cudaGetSymbolAddress((void**)&U2, g_U2);
    cudaGetSymbolAddress((void**)&U3, g_U3);
    cudaGetSymbolAddress((void**)&I0, g_I0);
    cudaGetSymbolAddress((void**)&I1, g_I1);
    cudaGetSymbolAddress((void**)&P1, g_P1);
    cudaGetSymbolAddress((void**)&P2, g_P2);
    cudaGetSymbolAddress((void**)&H1, g_H1);
    cudaGetSymbolAddress((void**)&H2, g_H2);
    cudaGetSymbolAddress((void**)&A,  g_A);
    cudaGetSymbolAddress((void**)&B,  g_B);
    cudaGetSymbolAddress((void**)&S1, g_S1);
    cudaGetSymbolAddress((void**)&S2, g_S2);
    cudaGetSymbolAddress((void**)&S3, g_S3);
    cudaGetSymbolAddress((void**)&S4, g_S4);

    const int T = 256;
    int half_r = (ne_rate + 1) / 2;
    int gb_l1 = (half_r * 8 + T - 1) / T;
    int slots_l2 = (half_r > ne_trust) ? half_r : ne_trust;
    int gb_l2 = (slots_l2 * 8 + T - 1) / T;

    // persistent block counts (multiples of SM count 148)
    const int NBU = 592;   // user segment of proj_all (4 waves)
    const int NBI = 296;   // item segment of proj_all
    const int NBA = 296;   // projHH segment A (ni rows)
    const int NBB = 592;   // projHH segment B (nu rows)
    const int NBH = 592;   // head

    // all 6 input projections + scratch zeroing in one persistent segmented launch
    proj_all_kernel<<<NBU + NBI, T>>>(user, p[0], p[1], p[7], p[8], p[12], p[13], p[17], p[18],
                                      U0, U1, U2, U3, nu, NBU,
                                      item, p[2], p[3], p[5], p[6], I0, I1, ni);

    // layer 1 fused edge pass (rate + rated-by share the edge list), 2 edges/thread
    edge_l1_kernel<<<gb_l1, T>>>(rate_src, rate_dst,
                                 (const float4*)U0, (const float4*)I0, (const float4*)p[4], H1, S1,
                                 (const float4*)I1, (const float4*)U1, (const float4*)p[9], H2, S2,
                                 ne_rate, half_r);

    // layer-2 src projections (normalization folded via S1/S2), persistent
    projHH_kernel<<<NBA + NBB, T>>>(H1, S1, p[10], p[11], P1, ni, NBA,
                                    H2, S2, p[15], p[16], P2, nu);

    // layer-2 edge pass: rby (2 edges/thread) + trust (1 edge/thread)
    edge_l2_kernel<<<gb_l2, T>>>(
        rate_dst, rate_src, (const float4*)P1, (const float4*)U2, (const float4*)p[14], A, S3,
        ne_rate, half_r,
        trust_src, trust_dst, (const float4*)P2, (const float4*)U3, (const float4*)p[19], B, S4,
        ne_trust);

    // head (+fused BN stats) + finalize (vectorized)
    head_kernel<<<NBH, T>>>(A, B, S3, S4, Wout, bout, y, nu);
    finalize_kernel<<<(nu * 8 + T - 1) / T, T>>>(y, gamma, beta, nu);
}